// round 1
// baseline (speedup 1.0000x reference)
#include <cuda_runtime.h>

// FIR: out[b,t,c] = sum_{i=0..15} w[i,c] * x[b, t-15+i, c]   (causal, zero-padded)
// x: [B=64, T=2048, C=32] fp32, w: [F=16, C=32] fp32, out: [B, T, C] fp32.

#define B_SZ 64
#define T_SZ 2048
#define C_SZ 32
#define F_SZ 16
#define CHUNK 64          // timesteps per thread
#define WARPS_PER_BLOCK 4 // blockDim.y

__global__ __launch_bounds__(C_SZ * WARPS_PER_BLOCK)
void fir_kernel(const float* __restrict__ x,
                const float* __restrict__ w,
                float* __restrict__ out) {
    const int c     = threadIdx.x;                         // lane = channel -> coalesced
    const int chunk = blockIdx.y * WARPS_PER_BLOCK + threadIdx.y;
    const int b     = blockIdx.x;
    const int t0    = chunk * CHUNK;

    // Per-channel taps into registers (coalesced, L2/L1-hot after first warp).
    float wr[F_SZ];
#pragma unroll
    for (int i = 0; i < F_SZ; i++) wr[i] = w[i * C_SZ + c];

    const float* xb = x   + ((size_t)b * T_SZ + t0) * C_SZ + c;
    float*       ob = out + ((size_t)b * T_SZ + t0) * C_SZ + c;

    // Ring buffer: slot s holds x[t] with t % 16 == s.
    // Preload history x[t0-15 .. t0-1] into slots 1..15 (t0 is a multiple of 16).
    float win[F_SZ];
    win[0] = 0.0f;
#pragma unroll
    for (int s = 1; s < F_SZ; s++) {
        const int t = t0 - F_SZ + s;
        win[s] = (t >= 0) ? xb[(s - F_SZ) * C_SZ] : 0.0f;
    }

    // out[t] = sum_i wr[i] * win[(u + 1 + i) & 15]  where u = t % 16,
    // after storing x[t] into win[u]. Unroll by 16 so all ring indices are static.
#pragma unroll 1
    for (int o = 0; o < CHUNK / F_SZ; o++) {
#pragma unroll
        for (int u = 0; u < F_SZ; u++) {
            const int tt = o * F_SZ + u;
            win[u] = xb[tt * C_SZ];
            // Two accumulator chains to cut the FFMA dependency depth 16 -> 8.
            float acc0 = 0.0f, acc1 = 0.0f;
#pragma unroll
            for (int i = 0; i < F_SZ; i += 2) {
                acc0 = fmaf(wr[i],     win[(u + 1 + i) & (F_SZ - 1)], acc0);
                acc1 = fmaf(wr[i + 1], win[(u + 2 + i) & (F_SZ - 1)], acc1);
            }
            ob[tt * C_SZ] = acc0 + acc1;
        }
    }
}

extern "C" void kernel_launch(void* const* d_in, const int* in_sizes, int n_in,
                              void* d_out, int out_size) {
    const float* x = (const float*)d_in[0];   // [64, 2048, 32]
    const float* w = (const float*)d_in[1];   // [16, 32]
    float* out = (float*)d_out;

    dim3 block(C_SZ, WARPS_PER_BLOCK);                       // 128 threads
    dim3 grid(B_SZ, (T_SZ / CHUNK) / WARPS_PER_BLOCK);       // (64, 8) = 512 blocks
    fir_kernel<<<grid, block>>>(x, w, out);
}